// round 1
// baseline (speedup 1.0000x reference)
#include <cuda_runtime.h>
#include <math.h>

#define NR 32768
#define NH 8
#define DD 128
#define HD 1024     // NH * DD
#define KCH 32      // split-K chunks for ktv

// ---------------- scratch (static device memory; no allocations) ----------------
__device__ float g_Wq[DD * HD];          // [i][h*128+o]
__device__ float g_Wk[DD * HD];
__device__ float g_Wv[DD * HD];
__device__ float g_Wvm[DD * DD];         // mean_h Wv_w[h][d][i]  -> [d][i]
__device__ float g_Wfuse[DD * DD];       // [i][o]
__device__ float g_cfuse[DD];
__device__ float g_bufA[(size_t)NR * HD];  // raw ks -> phi_ks ; then raw qs -> phi_qs
__device__ float g_bufB[(size_t)NR * HD];  // v ; then num
__device__ float g_att[(size_t)NR * DD];   // fused vss mean
__device__ float g_ktv[NH * DD * DD];      // [h][m][d]
__device__ float g_ksum[NH * DD];          // [h][m]
__device__ float g_ktvp[(size_t)KCH * NH * DD * DD];
__device__ float g_ksump[KCH * NH * DD];

// ---------------- weight repack + Wv head-mean ----------------
__global__ void prep_kernel(const float* __restrict__ Wq,
                            const float* __restrict__ Wk,
                            const float* __restrict__ Wv) {
    int idx = blockIdx.x * blockDim.x + threadIdx.x;
    if (idx < 3 * 131072) {
        int which = idx / 131072;
        int e = idx % 131072;            // e = (h*128+o)*128 + i
        int i = e & 127, ho = e >> 7;
        const float* src = (which == 0) ? Wq : (which == 1) ? Wk : Wv;
        float* dst = (which == 0) ? g_Wq : (which == 1) ? g_Wk : g_Wv;
        dst[i * HD + ho] = src[e];
    } else if (idx < 3 * 131072 + DD * DD) {
        int e = idx - 3 * 131072;
        int i = e & 127, d = e >> 7;
        float s = 0.f;
        #pragma unroll
        for (int h = 0; h < NH; h++) s += Wv[((size_t)(h * DD + d)) * DD + i];
        g_Wvm[d * DD + i] = s * 0.125f;
    }
}

// Wfuse[i][o] = sum_d Wvm[d][i] * vmw[o][d]; cfuse[o] = sum_d bvmean[d]*vmw[o][d] + vmb[o]
__global__ void wfuse_kernel(const float* __restrict__ Wv_b,
                             const float* __restrict__ vmw,
                             const float* __restrict__ vmb) {
    int idx = blockIdx.x * blockDim.x + threadIdx.x;  // 0..16383
    if (idx >= DD * DD) return;
    int o = idx & 127, i = idx >> 7;
    float acc = 0.f;
    for (int d = 0; d < DD; d++) acc += g_Wvm[d * DD + i] * vmw[o * DD + d];
    g_Wfuse[i * DD + o] = acc;
    if (idx < DD) {
        float c = 0.f;
        for (int d = 0; d < DD; d++) {
            float bm = 0.f;
            #pragma unroll
            for (int h = 0; h < NH; h++) bm += Wv_b[h * DD + d];
            c += 0.125f * bm * vmw[idx * DD + d];
        }
        g_cfuse[idx] = c + vmb[idx];
    }
}

// ---------------- generic fp32 tiled GEMM ----------------
// C[r][colb+c] = sum_k A[r][a_off + k] * W[k][c] (+ bias[colb+c])
// PER_HEAD: blockIdx.y = head; a_off = head*128; W = Wbase + head*128*128, wstride=128.
template <bool PER_HEAD>
__global__ void __launch_bounds__(256)
gemm_kernel(const float* __restrict__ A, int lda,
            const float* __restrict__ W, int wstride,
            const float* __restrict__ bias,
            float* __restrict__ C, int ldc) {
    const int BM = 128, BN = 128, BK = 16;
    __shared__ float As[BK][BM];
    __shared__ float Ws[BK][BN];
    int tid = threadIdx.x;
    int tx = tid & 15, ty = tid >> 4;
    int row0 = blockIdx.x * BM;
    int colb = blockIdx.y * BN;

    const float* Wp;
    int a_off;
    if (PER_HEAD) { Wp = W + (size_t)blockIdx.y * DD * DD; a_off = blockIdx.y * DD; }
    else          { Wp = W + colb;                         a_off = 0; }

    float acc[8][8];
    #pragma unroll
    for (int i = 0; i < 8; i++)
        #pragma unroll
        for (int j = 0; j < 8; j++) acc[i][j] = 0.f;

    int arow = tid >> 1;            // 0..127
    int akoff = (tid & 1) * 8;      // 0 or 8
    int widx = tid * 2;             // 0..510  -> k = widx/32, c4 = widx%32
    int wk = widx >> 5;
    int wc = (widx & 31) * 4;

    for (int k0 = 0; k0 < 128; k0 += BK) {
        const float* ap = A + (size_t)(row0 + arow) * lda + a_off + k0 + akoff;
        float4 a0 = *(const float4*)ap;
        float4 a1 = *(const float4*)(ap + 4);
        As[akoff + 0][arow] = a0.x; As[akoff + 1][arow] = a0.y;
        As[akoff + 2][arow] = a0.z; As[akoff + 3][arow] = a0.w;
        As[akoff + 4][arow] = a1.x; As[akoff + 5][arow] = a1.y;
        As[akoff + 6][arow] = a1.z; As[akoff + 7][arow] = a1.w;

        const float* wp = Wp + (size_t)(k0 + wk) * wstride + wc;
        float4 b0 = *(const float4*)wp;
        float4 b1 = *(const float4*)(wp + 4);
        *(float4*)&Ws[wk][wc] = b0;
        *(float4*)&Ws[wk][wc + 4] = b1;
        __syncthreads();

        #pragma unroll
        for (int k = 0; k < BK; k++) {
            float a[8], b[8];
            #pragma unroll
            for (int i = 0; i < 8; i++) a[i] = As[k][ty * 8 + i];
            #pragma unroll
            for (int j = 0; j < 8; j++) b[j] = Ws[k][tx * 8 + j];
            #pragma unroll
            for (int i = 0; i < 8; i++)
                #pragma unroll
                for (int j = 0; j < 8; j++) acc[i][j] += a[i] * b[j];
        }
        __syncthreads();
    }

    float breg[8];
    #pragma unroll
    for (int j = 0; j < 8; j++) breg[j] = bias ? bias[colb + tx * 8 + j] : 0.f;

    #pragma unroll
    for (int i = 0; i < 8; i++) {
        int r = row0 + ty * 8 + i;
        float* cp = C + (size_t)r * ldc + colb + tx * 8;
        #pragma unroll
        for (int j = 0; j < 8; j += 4) {
            float4 v;
            v.x = acc[i][j + 0] + breg[j + 0];
            v.y = acc[i][j + 1] + breg[j + 1];
            v.z = acc[i][j + 2] + breg[j + 2];
            v.w = acc[i][j + 3] + breg[j + 3];
            *(float4*)(cp + j) = v;
        }
    }
}

// ---------------- phi: in-place over [NR][HD], one warp per (n, head) ----------------
__global__ void phi_kernel(float* __restrict__ buf, const float* __restrict__ norm_scale) {
    int n = blockIdx.x;
    int h = threadIdx.x >> 5;
    int lane = threadIdx.x & 31;
    float inv = 1.f / (fabsf(*norm_scale) + 1e-6f);
    float4* p = (float4*)(buf + (size_t)n * HD + h * DD) + lane;
    float4 x = *p;
    float y0 = (fmaxf(x.x, 0.f) + 1e-6f) * inv;
    float y1 = (fmaxf(x.y, 0.f) + 1e-6f) * inv;
    float y2 = (fmaxf(x.z, 0.f) + 1e-6f) * inv;
    float y3 = (fmaxf(x.w, 0.f) + 1e-6f) * inv;
    float q0 = y0 * y0, q1 = y1 * y1, q2 = y2 * y2, q3 = y3 * y3;
    float s2 = q0 + q1 + q2 + q3;                               // sum y^2
    float s4 = q0 * q0 + q1 * q1 + q2 * q2 + q3 * q3;           // sum y^4
    #pragma unroll
    for (int off = 16; off; off >>= 1) {
        s2 += __shfl_xor_sync(0xffffffffu, s2, off);
        s4 += __shfl_xor_sync(0xffffffffu, s4, off);
    }
    float r = sqrtf(s2) / (sqrtf(s4) + 1e-8f);
    float4 o;
    o.x = r * q0; o.y = r * q1; o.z = r * q2; o.w = r * q3;
    *p = o;
}

// ---------------- ktv partial: block = (head, chunk); 128x128 outer-product accum ----------------
__global__ void __launch_bounds__(256) ktv_partial_kernel() {
    int h = blockIdx.x;
    int chunk = blockIdx.y;
    __shared__ float Ps[16][DD];
    __shared__ float Vs[16][DD];
    int tid = threadIdx.x;
    int tx = tid & 15, ty = tid >> 4;
    float acc[8][8];
    #pragma unroll
    for (int i = 0; i < 8; i++)
        #pragma unroll
        for (int j = 0; j < 8; j++) acc[i][j] = 0.f;
    float ks = 0.f;

    int n0 = chunk * (NR / KCH);   // 1024 rows per chunk
    int lr = tid >> 4;             // 0..15
    int lc = (tid & 15) * 8;       // 0..120
    for (int nb = 0; nb < NR / KCH; nb += 16) {
        size_t base = (size_t)(n0 + nb + lr) * HD + h * DD + lc;
        float4 p0 = *(const float4*)(g_bufA + base);
        float4 p1 = *(const float4*)(g_bufA + base + 4);
        *(float4*)&Ps[lr][lc] = p0; *(float4*)&Ps[lr][lc + 4] = p1;
        float4 v0 = *(const float4*)(g_bufB + base);
        float4 v1 = *(const float4*)(g_bufB + base + 4);
        *(float4*)&Vs[lr][lc] = v0; *(float4*)&Vs[lr][lc + 4] = v1;
        __syncthreads();
        #pragma unroll
        for (int k = 0; k < 16; k++) {
            float a[8], b[8];
            #pragma unroll
            for (int i = 0; i < 8; i++) a[i] = Ps[k][ty * 8 + i];
            #pragma unroll
            for (int j = 0; j < 8; j++) b[j] = Vs[k][tx * 8 + j];
            #pragma unroll
            for (int i = 0; i < 8; i++)
                #pragma unroll
                for (int j = 0; j < 8; j++) acc[i][j] += a[i] * b[j];
        }
        if (tid < DD) {
            #pragma unroll
            for (int k = 0; k < 16; k++) ks += Ps[k][tid];
        }
        __syncthreads();
    }
    float* out = g_ktvp + ((size_t)chunk * NH + h) * (DD * DD);
    #pragma unroll
    for (int i = 0; i < 8; i++)
        #pragma unroll
        for (int j = 0; j < 8; j++)
            out[(ty * 8 + i) * DD + tx * 8 + j] = acc[i][j];
    if (tid < DD) g_ksump[(chunk * NH + h) * DD + tid] = ks;
}

__global__ void ktv_reduce_kernel() {
    int idx = blockIdx.x * blockDim.x + threadIdx.x;
    if (idx < NH * DD * DD) {
        float s = 0.f;
        #pragma unroll 8
        for (int c = 0; c < KCH; c++) s += g_ktvp[(size_t)c * NH * DD * DD + idx];
        g_ktv[idx] = s;
    }
    if (idx < NH * DD) {
        float s = 0.f;
        #pragma unroll 8
        for (int c = 0; c < KCH; c++) s += g_ksump[c * NH * DD + idx];
        g_ksum[idx] = s;
    }
}

// ---------------- combine: one warp per row -> out[n][129] ----------------
__global__ void combine_kernel(float* __restrict__ out) {
    int n = blockIdx.x * 8 + (threadIdx.x >> 5);
    int lane = threadIdx.x & 31;
    const float* phiq = g_bufA + (size_t)n * HD;
    const float* num  = g_bufB + (size_t)n * HD;

    float dinv[NH];
    #pragma unroll
    for (int h = 0; h < NH; h++) {
        float4 q = *((const float4*)(phiq + h * DD) + lane);
        float4 s = *((const float4*)(g_ksum + h * DD) + lane);
        float d = q.x * s.x + q.y * s.y + q.z * s.z + q.w * s.w;
        #pragma unroll
        for (int off = 16; off; off >>= 1) d += __shfl_xor_sync(0xffffffffu, d, off);
        dinv[h] = 1.f / (d + 1e-6f);
    }

    float vals[4];
    float ssum = 0.f;
    #pragma unroll
    for (int c = 0; c < 4; c++) {
        int dcol = c * 32 + lane;
        float acc = 0.f;
        #pragma unroll
        for (int h = 0; h < NH; h++) acc += num[h * DD + dcol] * dinv[h];
        acc = acc * 0.125f + g_att[(size_t)n * DD + dcol];
        vals[c] = acc;
        ssum += acc * acc;
    }
    #pragma unroll
    for (int off = 16; off; off >>= 1) ssum += __shfl_xor_sync(0xffffffffu, ssum, off);
    float t = sqrtf(ssum + 1.0f);   // MANIFOLD_K = 1.0

    float* op = out + (size_t)n * 129;
    if (lane == 0) op[0] = t;
    #pragma unroll
    for (int c = 0; c < 4; c++) op[1 + c * 32 + lane] = vals[c];
}

// ---------------- launch ----------------
extern "C" void kernel_launch(void* const* d_in, const int* in_sizes, int n_in,
                              void* d_out, int out_size) {
    const float* xq   = (const float*)d_in[0];
    const float* xs   = (const float*)d_in[1];
    const float* Wq_w = (const float*)d_in[2];
    const float* Wq_b = (const float*)d_in[3];
    const float* Wk_w = (const float*)d_in[4];
    const float* Wk_b = (const float*)d_in[5];
    const float* Wv_w = (const float*)d_in[6];
    const float* Wv_b = (const float*)d_in[7];
    const float* vmw  = (const float*)d_in[8];
    const float* vmb  = (const float*)d_in[9];
    const float* nsc  = (const float*)d_in[10];
    float* out = (float*)d_out;

    float *pWq, *pWk, *pWv, *pWfuse, *pcfuse, *pbufA, *pbufB, *patt, *pktv;
    cudaGetSymbolAddress((void**)&pWq, g_Wq);
    cudaGetSymbolAddress((void**)&pWk, g_Wk);
    cudaGetSymbolAddress((void**)&pWv, g_Wv);
    cudaGetSymbolAddress((void**)&pWfuse, g_Wfuse);
    cudaGetSymbolAddress((void**)&pcfuse, g_cfuse);
    cudaGetSymbolAddress((void**)&pbufA, g_bufA);
    cudaGetSymbolAddress((void**)&pbufB, g_bufB);
    cudaGetSymbolAddress((void**)&patt, g_att);
    cudaGetSymbolAddress((void**)&pktv, g_ktv);

    // 1. weight repack + head-mean of Wv
    prep_kernel<<<(3 * 131072 + DD * DD + 255) / 256, 256>>>(Wq_w, Wk_w, Wv_w);
    // 2. fused vss weight
    wfuse_kernel<<<(DD * DD + 255) / 256, 256>>>(Wv_b, vmw, vmb);

    dim3 gproj(NR / 128, HD / 128);
    // 3. K projection -> bufA (raw)
    gemm_kernel<false><<<gproj, 256>>>(xs, DD, pWk, HD, Wk_b, pbufA, HD);
    // 4. V projection -> bufB
    gemm_kernel<false><<<gproj, 256>>>(xs, DD, pWv, HD, Wv_b, pbufB, HD);
    // 5. phi(ks) in place
    phi_kernel<<<NR, 256>>>(pbufA, nsc);
    // 6. ktv + ksum (deterministic two-stage)
    ktv_partial_kernel<<<dim3(NH, KCH), 256>>>();
    ktv_reduce_kernel<<<(NH * DD * DD + 255) / 256, 256>>>();
    // 7. Q projection -> bufA (overwrites phi_ks; ktv already consumed it)
    gemm_kernel<false><<<gproj, 256>>>(xq, DD, pWq, HD, Wq_b, pbufA, HD);
    // 8. phi(qs) in place
    phi_kernel<<<NR, 256>>>(pbufA, nsc);
    // 9. numerator: per-head phi_qs @ ktv[h] -> bufB (overwrites v)
    gemm_kernel<true><<<dim3(NR / 128, NH), 256>>>(pbufA, HD, pktv, DD, nullptr, pbufB, HD);
    // 10. fused vss: xs @ Wfuse + cfuse -> att
    gemm_kernel<false><<<dim3(NR / 128, 1), 256>>>(xs, DD, pWfuse, DD, pcfuse, patt, DD);
    // 11. combine + time coordinate -> out [NR][129]
    combine_kernel<<<NR / 8, 256>>>(out);
}

// round 3
// speedup vs baseline: 1.4427x; 1.4427x over previous
#include <cuda_runtime.h>
#include <cuda_bf16.h>
#include <cstdint>
#include <math.h>

#define NR 32768
#define NH 8
#define DD 128
#define HD 1024     // NH * DD
#define KCH 32      // split-K chunks for ktv

// ---------------- scratch (static device memory; no allocations) ----------------
__device__ __nv_bfloat16 g_Wqh[DD * HD], g_Wql[DD * HD];   // [h*128+o][i] K-major
__device__ __nv_bfloat16 g_Wkh[DD * HD], g_Wkl[DD * HD];
__device__ __nv_bfloat16 g_Wvh[DD * HD], g_Wvl[DD * HD];
__device__ float g_Wvm[DD * DD];                           // mean_h Wv_w -> [d][i]
__device__ __nv_bfloat16 g_WfTh[DD * DD], g_WfTl[DD * DD]; // fused vss weight [o][i] K-major
__device__ float g_cfuse[DD];
__device__ float g_bufA[(size_t)NR * HD];   // phi_ks ; then phi_qs
__device__ float g_bufB[(size_t)NR * HD];   // v ; then num
__device__ float g_att[(size_t)NR * DD];    // fused vss mean
__device__ __nv_bfloat16 g_ktvTh[NH * DD * DD], g_ktvTl[NH * DD * DD];  // [h][d][m]
__device__ float g_ksum[NH * DD];
__device__ float g_ktvp[(size_t)KCH * NH * DD * DD];
__device__ float g_ksump[KCH * NH * DD];

// ---------------- helpers ----------------
__device__ __forceinline__ uint32_t smem_u32(const void* p) {
    uint32_t a;
    asm("{ .reg .u64 t; cvta.to.shared.u64 t, %1; cvt.u32.u64 %0, t; }" : "=r"(a) : "l"(p));
    return a;
}
__device__ __forceinline__ uint32_t pack_bf2(__nv_bfloat16 a, __nv_bfloat16 b) {
    __nv_bfloat162 t; t.x = a; t.y = b;
    return *reinterpret_cast<uint32_t*>(&t);
}
__device__ __forceinline__ void split_bf(float x, __nv_bfloat16& h, __nv_bfloat16& l) {
    h = __float2bfloat16_rn(x);
    l = __float2bfloat16_rn(x - __bfloat162float(h));
}
// xor-swizzle for 256B-row bf16 panels: 16B chunk id (bits4-7) ^= row low 3 bits
#define SWZ(o) ((o) ^ ((((o) >> 8) & 7) << 4))

__device__ __forceinline__ void ldsm_x4(uint32_t& r0, uint32_t& r1, uint32_t& r2,
                                        uint32_t& r3, uint32_t addr) {
    asm volatile("ldmatrix.sync.aligned.m8n8.x4.shared.b16 {%0,%1,%2,%3}, [%4];"
                 : "=r"(r0), "=r"(r1), "=r"(r2), "=r"(r3) : "r"(addr));
}
__device__ __forceinline__ void mma_bf16(float* c, uint32_t a0, uint32_t a1,
                                         uint32_t a2, uint32_t a3,
                                         uint32_t b0, uint32_t b1) {
    asm volatile("mma.sync.aligned.m16n8k16.row.col.f32.bf16.bf16.f32 "
                 "{%0,%1,%2,%3}, {%4,%5,%6,%7}, {%8,%9}, {%0,%1,%2,%3};"
                 : "+f"(c[0]), "+f"(c[1]), "+f"(c[2]), "+f"(c[3])
                 : "r"(a0), "r"(a1), "r"(a2), "r"(a3), "r"(b0), "r"(b1));
}

// ---------------- weight prep: bf16 split + Wv head-mean ----------------
__global__ void prep_kernel(const float* __restrict__ Wq,
                            const float* __restrict__ Wk,
                            const float* __restrict__ Wv) {
    int idx = blockIdx.x * blockDim.x + threadIdx.x;
    if (idx < 3 * 131072) {
        int which = idx / 131072;
        int e = idx % 131072;   // e = (h*128+o)*128 + i (K-major already)
        const float* src = (which == 0) ? Wq : (which == 1) ? Wk : Wv;
        __nv_bfloat16 h, l;
        split_bf(src[e], h, l);
        if (which == 0)      { g_Wqh[e] = h; g_Wql[e] = l; }
        else if (which == 1) { g_Wkh[e] = h; g_Wkl[e] = l; }
        else                 { g_Wvh[e] = h; g_Wvl[e] = l; }
    } else if (idx < 3 * 131072 + DD * DD) {
        int e = idx - 3 * 131072;
        int i = e & 127, d = e >> 7;
        float s = 0.f;
        #pragma unroll
        for (int h = 0; h < NH; h++) s += Wv[((size_t)(h * DD + d)) * DD + i];
        g_Wvm[d * DD + i] = s * 0.125f;
    }
}

__global__ void wfuse_kernel(const float* __restrict__ Wv_b,
                             const float* __restrict__ vmw,
                             const float* __restrict__ vmb) {
    int idx = blockIdx.x * blockDim.x + threadIdx.x;
    if (idx >= DD * DD) return;
    int o = idx & 127, i = idx >> 7;
    float acc = 0.f;
    for (int d = 0; d < DD; d++) acc += g_Wvm[d * DD + i] * vmw[o * DD + d];
    __nv_bfloat16 h, l;
    split_bf(acc, h, l);
    g_WfTh[o * DD + i] = h;
    g_WfTl[o * DD + i] = l;
    if (idx < DD) {
        float c = 0.f;
        for (int d = 0; d < DD; d++) {
            float bm = 0.f;
            #pragma unroll
            for (int hh = 0; hh < NH; hh++) bm += Wv_b[hh * DD + d];
            c += 0.125f * bm * vmw[idx * DD + d];
        }
        g_cfuse[idx] = c + vmb[idx];
    }
}

// ---------------- mma.sync bf16-pair GEMM (+ optional fused phi) ----------------
// C[row][colb+c] = phi?( sum_k A[row][aoff+k]*B[colb+c][k] + bias )
// block: 128 rows x 128 cols, K=128 whole. 8 warps: wm in {0,1} (64 rows), wn in {0..3} (32 cols)
#define S_AH 0
#define S_AL 32768
#define S_BH 65536
#define S_BL 98304
#define MM_SMEM 131072
#define C_LD 132   // fp32 staging row stride (pad 4 to stagger banks)

__global__ void __launch_bounds__(256, 1) mm_gemm(
    const float* __restrict__ A, int lda, int per_head,
    const __nv_bfloat16* __restrict__ Bh, const __nv_bfloat16* __restrict__ Bl,
    const float* __restrict__ bias, float* __restrict__ C, int ldc,
    const float* __restrict__ nsc) {
    extern __shared__ __align__(16) char smem[];
    const uint32_t sb = smem_u32(smem);
    float* Cs = (float*)smem;
    const int tid = threadIdx.x;
    const int lane = tid & 31, warp = tid >> 5;
    const int wm = warp >> 2, wn = warp & 3;
    const int row0 = blockIdx.x * 128;
    const int colb = blockIdx.y * 128;
    const int aoff = per_head ? colb : 0;
    Bh += (size_t)colb * DD;
    Bl += (size_t)colb * DD;

    // ---- stage A: fp32 -> bf16 hi/lo ----
    #pragma unroll 4
    for (int it = 0; it < 16; it++) {
        int idx = it * 256 + tid;
        int r = idx >> 5, c4 = idx & 31;
        float4 av = *(const float4*)(A + (size_t)(row0 + r) * lda + aoff + c4 * 4);
        uint32_t off = SWZ((uint32_t)(r * 256 + c4 * 8));
        __nv_bfloat16 h0, h1, h2, h3, l0, l1, l2, l3;
        split_bf(av.x, h0, l0); split_bf(av.y, h1, l1);
        split_bf(av.z, h2, l2); split_bf(av.w, h3, l3);
        *(uint32_t*)(smem + S_AH + off)     = pack_bf2(h0, h1);
        *(uint32_t*)(smem + S_AH + off + 4) = pack_bf2(h2, h3);
        *(uint32_t*)(smem + S_AL + off)     = pack_bf2(l0, l1);
        *(uint32_t*)(smem + S_AL + off + 4) = pack_bf2(l2, l3);
    }
    // ---- stage B (pre-split bf16) ----
    #pragma unroll 4
    for (int it = 0; it < 8; it++) {
        int idx = it * 256 + tid;
        int r = idx >> 4, c16 = idx & 15;
        uint4 vh = *(const uint4*)(Bh + (size_t)r * DD + c16 * 8);
        uint4 vl = *(const uint4*)(Bl + (size_t)r * DD + c16 * 8);
        uint32_t off = SWZ((uint32_t)(r * 256 + c16 * 16));
        *(uint4*)(smem + S_BH + off) = vh;
        *(uint4*)(smem + S_BL + off) = vl;
    }
    __syncthreads();

    // ---- mma: 3 passes (AhBh, AhBl, AlBh) ----
    float acc[4][4][4];
    #pragma unroll
    for (int i = 0; i < 4; i++)
        #pragma unroll
        for (int j = 0; j < 4; j++)
            #pragma unroll
            for (int e = 0; e < 4; e++) acc[i][j][e] = 0.f;

    const uint32_t a_row = wm * 64 + (lane & 15);          // + mi*16
    const uint32_t a_cb  = (lane >> 4) * 16;               // + k0*2
    const uint32_t b_row = wn * 32 + (lane & 7) + ((lane >> 4) & 1) * 8;  // + nj*16
    const uint32_t b_cb  = ((lane >> 3) & 1) * 16;         // + k0*2

    #pragma unroll
    for (int pass = 0; pass < 3; pass++) {
        const uint32_t Ap = sb + ((pass == 2) ? S_AL : S_AH);
        const uint32_t Bp = sb + ((pass == 1) ? S_BL : S_BH);
        #pragma unroll
        for (int k = 0; k < 8; k++) {
            const uint32_t kb = k * 32;  // k0*2 bytes
            uint32_t a[4][4];
            #pragma unroll
            for (int mi = 0; mi < 4; mi++)
                ldsm_x4(a[mi][0], a[mi][1], a[mi][2], a[mi][3],
                        Ap + SWZ((a_row + mi * 16) * 256 + kb + a_cb));
            uint32_t b[2][4];
            #pragma unroll
            for (int nj = 0; nj < 2; nj++)
                ldsm_x4(b[nj][0], b[nj][1], b[nj][2], b[nj][3],
                        Bp + SWZ((b_row + nj * 16) * 256 + kb + b_cb));
            #pragma unroll
            for (int mi = 0; mi < 4; mi++)
                #pragma unroll
                for (int nb = 0; nb < 4; nb++)
                    mma_bf16(acc[mi][nb], a[mi][0], a[mi][1], a[mi][2], a[mi][3],
                             b[nb >> 1][(nb & 1) * 2], b[nb >> 1][(nb & 1) * 2 + 1]);
        }
    }
    __syncthreads();   // staging panels dead; reuse smem for C

    // ---- dump accumulators to smem ----
    {
        const int rr = wm * 64 + (lane >> 2);
        const int cc = wn * 32 + 2 * (lane & 3);
        #pragma unroll
        for (int mi = 0; mi < 4; mi++)
            #pragma unroll
            for (int nb = 0; nb < 4; nb++) {
                int r = rr + mi * 16;
                int c = cc + (nb >> 1) * 16 + (nb & 1) * 8;
                *(float2*)&Cs[r * C_LD + c]       = *(float2*)&acc[mi][nb][0];
                *(float2*)&Cs[(r + 8) * C_LD + c] = *(float2*)&acc[mi][nb][2];
            }
    }
    __syncthreads();

    // ---- epilogue ----
    if (nsc) {
        // fused phi: block cols = one full head; per-row norm over 128 cols
        float inv = 1.f / (fabsf(*nsc) + 1e-6f);
        const float4 bv = *(const float4*)(bias + colb + lane * 4);
        #pragma unroll 2
        for (int i = 0; i < 16; i++) {
            int r = warp * 16 + i;
            float4 x = *(float4*)&Cs[r * C_LD + lane * 4];
            float y0 = (fmaxf(x.x + bv.x, 0.f) + 1e-6f) * inv;
            float y1 = (fmaxf(x.y + bv.y, 0.f) + 1e-6f) * inv;
            float y2 = (fmaxf(x.z + bv.z, 0.f) + 1e-6f) * inv;
            float y3 = (fmaxf(x.w + bv.w, 0.f) + 1e-6f) * inv;
            float q0 = y0 * y0, q1 = y1 * y1, q2 = y2 * y2, q3 = y3 * y3;
            float s2 = q0 + q1 + q2 + q3;
            float s4 = q0 * q0 + q1 * q1 + q2 * q2 + q3 * q3;
            #pragma unroll
            for (int off = 16; off; off >>= 1) {
                s2 += __shfl_xor_sync(0xffffffffu, s2, off);
                s4 += __shfl_xor_sync(0xffffffffu, s4, off);
            }
            float rsc = sqrtf(s2) / (sqrtf(s4) + 1e-8f);
            float4 o;
            o.x = rsc * q0; o.y = rsc * q1; o.z = rsc * q2; o.w = rsc * q3;
            *(float4*)(C + (size_t)(row0 + r) * ldc + colb + lane * 4) = o;
        }
    } else {
        #pragma unroll 4
        for (int it = 0; it < 16; it++) {
            int idx = it * 256 + tid;
            int r = idx >> 5, c4 = idx & 31;
            float4 v = *(float4*)&Cs[r * C_LD + c4 * 4];
            if (bias) {
                const float4 bv = *(const float4*)(bias + colb + c4 * 4);
                v.x += bv.x; v.y += bv.y; v.z += bv.z; v.w += bv.w;
            }
            *(float4*)(C + (size_t)(row0 + r) * ldc + colb + c4 * 4) = v;
        }
    }
}

// ---------------- ktv partial: block = (head, chunk) ----------------
__global__ void __launch_bounds__(256) ktv_partial_kernel() {
    int h = blockIdx.x;
    int chunk = blockIdx.y;
    __shared__ float Ps[16][DD];
    __shared__ float Vs[16][DD];
    int tid = threadIdx.x;
    int tx = tid & 15, ty = tid >> 4;
    float acc[8][8];
    #pragma unroll
    for (int i = 0; i < 8; i++)
        #pragma unroll
        for (int j = 0; j < 8; j++) acc[i][j] = 0.f;
    float ks = 0.f;

    int n0 = chunk * (NR / KCH);
    int lr = tid >> 4;
    int lc = (tid & 15) * 8;
    for (int nb = 0; nb < NR / KCH; nb += 16) {
        size_t base = (size_t)(n0 + nb + lr) * HD + h * DD + lc;
        float4 p0 = *(const float4*)(g_bufA + base);
        float4 p1 = *(const float4*)(g_bufA + base + 4);
        *(float4*)&Ps[lr][lc] = p0; *(float4*)&Ps[lr][lc + 4] = p1;
        float4 v0 = *(const float4*)(g_bufB + base);
        float4 v1 = *(const float4*)(g_bufB + base + 4);
        *(float4*)&Vs[lr][lc] = v0; *(float4*)&Vs[lr][lc + 4] = v1;
        __syncthreads();
        #pragma unroll
        for (int k = 0; k < 16; k++) {
            float a[8], b[8];
            #pragma unroll
            for (int i = 0; i < 8; i++) a[i] = Ps[k][ty * 8 + i];
            #pragma unroll
            for (int j = 0; j < 8; j++) b[j] = Vs[k][tx * 8 + j];
            #pragma unroll
            for (int i = 0; i < 8; i++)
                #pragma unroll
                for (int j = 0; j < 8; j++) acc[i][j] += a[i] * b[j];
        }
        if (tid < DD) {
            #pragma unroll
            for (int k = 0; k < 16; k++) ks += Ps[k][tid];
        }
        __syncthreads();
    }
    float* out = g_ktvp + ((size_t)chunk * NH + h) * (DD * DD);
    #pragma unroll
    for (int i = 0; i < 8; i++)
        #pragma unroll
        for (int j = 0; j < 8; j++)
            out[(ty * 8 + i) * DD + tx * 8 + j] = acc[i][j];
    if (tid < DD) g_ksump[(chunk * NH + h) * DD + tid] = ks;
}

// reduce partials; write ktv^T bf16-split for the numerator GEMM
__global__ void ktv_reduce_kernel() {
    int idx = blockIdx.x * blockDim.x + threadIdx.x;
    if (idx < NH * DD * DD) {
        float s = 0.f;
        #pragma unroll 8
        for (int c = 0; c < KCH; c++) s += g_ktvp[(size_t)c * NH * DD * DD + idx];
        int h = idx >> 14, m = (idx >> 7) & 127, d = idx & 127;
        __nv_bfloat16 hi, lo;
        split_bf(s, hi, lo);
        g_ktvTh[(h << 14) + (d << 7) + m] = hi;
        g_ktvTl[(h << 14) + (d << 7) + m] = lo;
    }
    if (idx < NH * DD) {
        float s = 0.f;
        #pragma unroll 8
        for (int c = 0; c < KCH; c++) s += g_ksump[c * NH * DD + idx];
        g_ksum[idx] = s;
    }
}

// ---------------- combine: one warp per row -> out[n][129] ----------------
__global__ void combine_kernel(float* __restrict__ out) {
    int n = blockIdx.x * 8 + (threadIdx.x >> 5);
    int lane = threadIdx.x & 31;
    const float* phiq = g_bufA + (size_t)n * HD;
    const float* num  = g_bufB + (size_t)n * HD;

    float dinv[NH];
    #pragma unroll
    for (int h = 0; h < NH; h++) {
        float4 q = *((const float4*)(phiq + h * DD) + lane);
        float4 s = *((const float4*)(g_ksum + h * DD) + lane);
        float d = q.x * s.x + q.y * s.y + q.z * s.z + q.w * s.w;
        #pragma unroll
        for (int off = 16; off; off >>= 1) d += __shfl_xor_sync(0xffffffffu, d, off);
        dinv[h] = 1.f / (d + 1e-6f);
    }

    float vals[4];
    float ssum = 0.f;
    #pragma unroll
    for (int c = 0; c < 4; c++) {
        int dcol = c * 32 + lane;
        float acc = 0.f;
        #pragma unroll
        for (int h = 0; h < NH; h++) acc += num[h * DD + dcol] * dinv[h];
        acc = acc * 0.125f + g_att[(size_t)n * DD + dcol];
        vals[c] = acc;
        ssum += acc * acc;
    }
    #pragma unroll
    for (int off = 16; off; off >>= 1) ssum += __shfl_xor_sync(0xffffffffu, ssum, off);
    float t = sqrtf(ssum + 1.0f);

    float* op = out + (size_t)n * 129;
    if (lane == 0) op[0] = t;
    #pragma unroll
    for (int c = 0; c < 4; c++) op[1 + c * 32 + lane] = vals[c];
}

// ---------------- launch ----------------
extern "C" void kernel_launch(void* const* d_in, const int* in_sizes, int n_in,
                              void* d_out, int out_size) {
    const float* xq   = (const float*)d_in[0];
    const float* xs   = (const float*)d_in[1];
    const float* Wq_w = (const float*)d_in[2];
    const float* Wq_b = (const float*)d_in[3];
    const float* Wk_w = (const float*)d_in[4];
    const float* Wk_b = (const float*)d_in[5];
    const float* Wv_w = (const float*)d_in[6];
    const float* Wv_b = (const float*)d_in[7];
    const float* vmw  = (const float*)d_in[8];
    const float* vmb  = (const float*)d_in[9];
    const float* nsc  = (const float*)d_in[10];
    float* out = (float*)d_out;

    float *pcfuse, *pbufA, *pbufB, *patt;
    __nv_bfloat16 *pWqh, *pWql, *pWkh, *pWkl, *pWvh, *pWvl, *pWfh, *pWfl, *pKTh, *pKTl;
    cudaGetSymbolAddress((void**)&pcfuse, g_cfuse);
    cudaGetSymbolAddress((void**)&pbufA, g_bufA);
    cudaGetSymbolAddress((void**)&pbufB, g_bufB);
    cudaGetSymbolAddress((void**)&patt, g_att);
    cudaGetSymbolAddress((void**)&pWqh, g_Wqh);
    cudaGetSymbolAddress((void**)&pWql, g_Wql);
    cudaGetSymbolAddress((void**)&pWkh, g_Wkh);
    cudaGetSymbolAddress((void**)&pWkl, g_Wkl);
    cudaGetSymbolAddress((void**)&pWvh, g_Wvh);
    cudaGetSymbolAddress((void**)&pWvl, g_Wvl);
    cudaGetSymbolAddress((void**)&pWfh, g_WfTh);
    cudaGetSymbolAddress((void**)&pWfl, g_WfTl);
    cudaGetSymbolAddress((void**)&pKTh, g_ktvTh);
    cudaGetSymbolAddress((void**)&pKTl, g_ktvTl);

    cudaFuncSetAttribute(mm_gemm, cudaFuncAttributeMaxDynamicSharedMemorySize, MM_SMEM);

    // 1. weight split + Wv head-mean
    prep_kernel<<<(3 * 131072 + DD * DD + 255) / 256, 256>>>(Wq_w, Wk_w, Wv_w);
    // 2. fused vss weight
    wfuse_kernel<<<(DD * DD + 255) / 256, 256>>>(Wv_b, vmw, vmb);

    dim3 gproj(NR / 128, NH);
    // 3. K projection + fused phi -> bufA
    mm_gemm<<<gproj, 256, MM_SMEM>>>(xs, DD, 0, pWkh, pWkl, Wk_b, pbufA, HD, nsc);
    // 4. V projection -> bufB
    mm_gemm<<<gproj, 256, MM_SMEM>>>(xs, DD, 0, pWvh, pWvl, Wv_b, pbufB, HD, nullptr);
    // 5. ktv + ksum (deterministic two-stage)
    ktv_partial_kernel<<<dim3(NH, KCH), 256>>>();
    ktv_reduce_kernel<<<(NH * DD * DD + 255) / 256, 256>>>();
    // 6. Q projection + fused phi -> bufA (phi_ks consumed)
    mm_gemm<<<gproj, 256, MM_SMEM>>>(xq, DD, 0, pWqh, pWql, Wq_b, pbufA, HD, nsc);
    // 7. numerator: per-head phi_qs @ ktv[h] -> bufB
    mm_gemm<<<gproj, 256, MM_SMEM>>>(pbufA, HD, 1, pKTh, pKTl, nullptr, pbufB, HD, nullptr);
    // 8. fused vss: xs @ WfuseT -> att
    mm_gemm<<<dim3(NR / 128, 1), 256, MM_SMEM>>>(xs, DD, 0, pWfh, pWfl, pcfuse, patt, DD, nullptr);
    // 9. combine + time coordinate -> out [NR][129]
    combine_kernel<<<NR / 8, 256>>>(out);
}

// round 4
// speedup vs baseline: 1.5711x; 1.0891x over previous
#include <cuda_runtime.h>
#include <cuda_bf16.h>
#include <cstdint>
#include <math.h>

#define NR 32768
#define NH 8
#define DD 128
#define HD 1024     // NH * DD
#define KC2 64      // split-K chunks for ktv (512 rows each)

// ---------------- scratch (static device memory; no allocations) ----------------
__device__ __nv_bfloat16 g_Wqh[DD * HD], g_Wql[DD * HD];   // [h*128+o][i] K-major
__device__ __nv_bfloat16 g_Wkh[DD * HD], g_Wkl[DD * HD];
__device__ __nv_bfloat16 g_Wvh[DD * HD], g_Wvl[DD * HD];
__device__ float g_Wvm[DD * DD];                           // mean_h Wv_w -> [d][i]
__device__ __nv_bfloat16 g_WfTh[DD * DD], g_WfTl[DD * DD]; // fused vss weight [o][i]
__device__ float g_cfuse[DD];
__device__ float g_bufA[(size_t)NR * HD];   // phi_qs (fp32)
__device__ float g_bufB[(size_t)NR * HD];   // num
__device__ float g_att[(size_t)NR * DD];    // fused vss mean
__device__ __nv_bfloat16 g_Kh[(size_t)NR * HD], g_Kl[(size_t)NR * HD];  // phi_ks split
__device__ __nv_bfloat16 g_Vh[(size_t)NR * HD], g_Vl[(size_t)NR * HD];  // v split
__device__ __nv_bfloat16 g_ktvTh[NH * DD * DD], g_ktvTl[NH * DD * DD];  // [h][d][m]
__device__ float g_ksum[NH * DD];
__device__ float g_ktvp[(size_t)KC2 * NH * DD * DD];
__device__ float g_ksump[KC2 * NH * DD];

// ---------------- helpers ----------------
__device__ __forceinline__ uint32_t smem_u32(const void* p) {
    uint32_t a;
    asm("{ .reg .u64 t; cvta.to.shared.u64 t, %1; cvt.u32.u64 %0, t; }" : "=r"(a) : "l"(p));
    return a;
}
__device__ __forceinline__ uint32_t pack_bf2(__nv_bfloat16 a, __nv_bfloat16 b) {
    __nv_bfloat162 t; t.x = a; t.y = b;
    return *reinterpret_cast<uint32_t*>(&t);
}
__device__ __forceinline__ void split_bf(float x, __nv_bfloat16& h, __nv_bfloat16& l) {
    h = __float2bfloat16_rn(x);
    l = __float2bfloat16_rn(x - __bfloat162float(h));
}
// swizzles: 256B-row panels and 128B-row panels (16B granule xor by row low bits)
#define SWZ(o)  ((o) ^ ((((o) >> 8) & 7) << 4))
#define SWZ1(o) ((o) ^ ((((o) >> 7) & 7) << 4))

__device__ __forceinline__ void ldsm_x4(uint32_t& r0, uint32_t& r1, uint32_t& r2,
                                        uint32_t& r3, uint32_t addr) {
    asm volatile("ldmatrix.sync.aligned.m8n8.x4.shared.b16 {%0,%1,%2,%3}, [%4];"
                 : "=r"(r0), "=r"(r1), "=r"(r2), "=r"(r3) : "r"(addr));
}
__device__ __forceinline__ void ldsm_x4_t(uint32_t& r0, uint32_t& r1, uint32_t& r2,
                                          uint32_t& r3, uint32_t addr) {
    asm volatile("ldmatrix.sync.aligned.m8n8.x4.trans.shared.b16 {%0,%1,%2,%3}, [%4];"
                 : "=r"(r0), "=r"(r1), "=r"(r2), "=r"(r3) : "r"(addr));
}
__device__ __forceinline__ void mma_bf16(float* c, uint32_t a0, uint32_t a1,
                                         uint32_t a2, uint32_t a3,
                                         uint32_t b0, uint32_t b1) {
    asm volatile("mma.sync.aligned.m16n8k16.row.col.f32.bf16.bf16.f32 "
                 "{%0,%1,%2,%3}, {%4,%5,%6,%7}, {%8,%9}, {%0,%1,%2,%3};"
                 : "+f"(c[0]), "+f"(c[1]), "+f"(c[2]), "+f"(c[3])
                 : "r"(a0), "r"(a1), "r"(a2), "r"(a3), "r"(b0), "r"(b1));
}

// ---------------- weight prep ----------------
__global__ void prep_kernel(const float* __restrict__ Wq,
                            const float* __restrict__ Wk,
                            const float* __restrict__ Wv) {
    int idx = blockIdx.x * blockDim.x + threadIdx.x;
    if (idx < 3 * 131072) {
        int which = idx / 131072;
        int e = idx % 131072;
        const float* src = (which == 0) ? Wq : (which == 1) ? Wk : Wv;
        __nv_bfloat16 h, l;
        split_bf(src[e], h, l);
        if (which == 0)      { g_Wqh[e] = h; g_Wql[e] = l; }
        else if (which == 1) { g_Wkh[e] = h; g_Wkl[e] = l; }
        else                 { g_Wvh[e] = h; g_Wvl[e] = l; }
    } else if (idx < 3 * 131072 + DD * DD) {
        int e = idx - 3 * 131072;
        int i = e & 127, d = e >> 7;
        float s = 0.f;
        #pragma unroll
        for (int h = 0; h < NH; h++) s += Wv[((size_t)(h * DD + d)) * DD + i];
        g_Wvm[d * DD + i] = s * 0.125f;
    }
}

__global__ void wfuse_kernel(const float* __restrict__ Wv_b,
                             const float* __restrict__ vmw,
                             const float* __restrict__ vmb) {
    int idx = blockIdx.x * blockDim.x + threadIdx.x;
    if (idx >= DD * DD) return;
    int o = idx & 127, i = idx >> 7;
    float acc = 0.f;
    for (int d = 0; d < DD; d++) acc += g_Wvm[d * DD + i] * vmw[o * DD + d];
    __nv_bfloat16 h, l;
    split_bf(acc, h, l);
    g_WfTh[o * DD + i] = h;
    g_WfTl[o * DD + i] = l;
    if (idx < DD) {
        float c = 0.f;
        for (int d = 0; d < DD; d++) {
            float bm = 0.f;
            #pragma unroll
            for (int hh = 0; hh < NH; hh++) bm += Wv_b[hh * DD + d];
            c += 0.125f * bm * vmw[idx * DD + d];
        }
        g_cfuse[idx] = c + vmb[idx];
    }
}

// ---------------- mma.sync bf16-pair GEMM, k-chunked for occupancy ----------------
// modes: Cf!=0 -> fp32 out; OutH!=0 -> bf16-split out; nsc!=0 -> fused phi (per-head cols)
#define S_AH 0
#define S_AL 16384
#define S_BH 32768
#define S_BL 49152
#define C_LD 132
#define MM_SMEM (128 * C_LD * 4)   // 67584 > 65536 panel bytes

__global__ void __launch_bounds__(256, 2) mm_gemm(
    const float* __restrict__ A, int lda, int per_head,
    const __nv_bfloat16* __restrict__ Bh, const __nv_bfloat16* __restrict__ Bl,
    const float* __restrict__ bias, float* __restrict__ Cf, int ldc,
    const float* __restrict__ nsc,
    __nv_bfloat16* __restrict__ OutH, __nv_bfloat16* __restrict__ OutL) {
    extern __shared__ __align__(16) char smem[];
    const uint32_t sb = smem_u32(smem);
    float* Cs = (float*)smem;
    const int tid = threadIdx.x;
    const int lane = tid & 31, warp = tid >> 5;
    const int wm = warp >> 2, wn = warp & 3;
    const int row0 = blockIdx.x * 128;
    const int colb = blockIdx.y * 128;
    const int aoff = per_head ? colb : 0;
    Bh += (size_t)colb * DD;
    Bl += (size_t)colb * DD;

    float acc[4][4][4];
    #pragma unroll
    for (int i = 0; i < 4; i++)
        #pragma unroll
        for (int j = 0; j < 4; j++)
            #pragma unroll
            for (int e = 0; e < 4; e++) acc[i][j][e] = 0.f;

    const uint32_t a_row = wm * 64 + (lane & 15);
    const uint32_t a_cb  = (lane >> 4) * 16;
    const uint32_t b_row = wn * 32 + (lane & 7) + ((lane >> 4) & 1) * 8;
    const uint32_t b_cb  = ((lane >> 3) & 1) * 16;

    #pragma unroll
    for (int kc = 0; kc < 2; kc++) {
        // stage A chunk: 128 x 64 fp32 -> bf16 hi/lo (128B swizzled rows)
        #pragma unroll 2
        for (int it = 0; it < 8; it++) {
            int idx = it * 256 + tid;
            int r = idx >> 4, c4 = idx & 15;
            float4 av = *(const float4*)(A + (size_t)(row0 + r) * lda + aoff + kc * 64 + c4 * 4);
            uint32_t off = SWZ1((uint32_t)(r * 128 + c4 * 8));
            __nv_bfloat16 h0, h1, h2, h3, l0, l1, l2, l3;
            split_bf(av.x, h0, l0); split_bf(av.y, h1, l1);
            split_bf(av.z, h2, l2); split_bf(av.w, h3, l3);
            *(uint32_t*)(smem + S_AH + off)     = pack_bf2(h0, h1);
            *(uint32_t*)(smem + S_AH + off + 4) = pack_bf2(h2, h3);
            *(uint32_t*)(smem + S_AL + off)     = pack_bf2(l0, l1);
            *(uint32_t*)(smem + S_AL + off + 4) = pack_bf2(l2, l3);
        }
        // stage B chunk (pre-split bf16): 128 x 64
        #pragma unroll 2
        for (int it = 0; it < 4; it++) {
            int idx = it * 256 + tid;
            int r = idx >> 3, c8 = idx & 7;
            uint4 vh = *(const uint4*)(Bh + (size_t)r * DD + kc * 64 + c8 * 8);
            uint4 vl = *(const uint4*)(Bl + (size_t)r * DD + kc * 64 + c8 * 8);
            uint32_t off = SWZ1((uint32_t)(r * 128 + c8 * 16));
            *(uint4*)(smem + S_BH + off) = vh;
            *(uint4*)(smem + S_BL + off) = vl;
        }
        __syncthreads();

        #pragma unroll
        for (int pass = 0; pass < 3; pass++) {
            const uint32_t Ap = sb + ((pass == 2) ? S_AL : S_AH);
            const uint32_t Bp = sb + ((pass == 1) ? S_BL : S_BH);
            #pragma unroll
            for (int k = 0; k < 4; k++) {
                const uint32_t kb = k * 32;
                uint32_t a[4][4];
                #pragma unroll
                for (int mi = 0; mi < 4; mi++)
                    ldsm_x4(a[mi][0], a[mi][1], a[mi][2], a[mi][3],
                            Ap + SWZ1((a_row + mi * 16) * 128 + kb + a_cb));
                uint32_t b[2][4];
                #pragma unroll
                for (int nj = 0; nj < 2; nj++)
                    ldsm_x4(b[nj][0], b[nj][1], b[nj][2], b[nj][3],
                            Bp + SWZ1((b_row + nj * 16) * 128 + kb + b_cb));
                #pragma unroll
                for (int mi = 0; mi < 4; mi++)
                    #pragma unroll
                    for (int nb = 0; nb < 4; nb++)
                        mma_bf16(acc[mi][nb], a[mi][0], a[mi][1], a[mi][2], a[mi][3],
                                 b[nb >> 1][(nb & 1) * 2], b[nb >> 1][(nb & 1) * 2 + 1]);
            }
        }
        __syncthreads();
    }

    // ---- dump accumulators to smem ----
    {
        const int rr = wm * 64 + (lane >> 2);
        const int cc = wn * 32 + 2 * (lane & 3);
        #pragma unroll
        for (int mi = 0; mi < 4; mi++)
            #pragma unroll
            for (int nb = 0; nb < 4; nb++) {
                int r = rr + mi * 16;
                int c = cc + (nb >> 1) * 16 + (nb & 1) * 8;
                *(float2*)&Cs[r * C_LD + c]       = *(float2*)&acc[mi][nb][0];
                *(float2*)&Cs[(r + 8) * C_LD + c] = *(float2*)&acc[mi][nb][2];
            }
    }
    __syncthreads();

    // ---- epilogue ----
    if (nsc) {
        float inv = 1.f / (fabsf(*nsc) + 1e-6f);
        const float4 bv = *(const float4*)(bias + colb + lane * 4);
        #pragma unroll 2
        for (int i = 0; i < 16; i++) {
            int r = warp * 16 + i;
            float4 x = *(float4*)&Cs[r * C_LD + lane * 4];
            float y0 = (fmaxf(x.x + bv.x, 0.f) + 1e-6f) * inv;
            float y1 = (fmaxf(x.y + bv.y, 0.f) + 1e-6f) * inv;
            float y2 = (fmaxf(x.z + bv.z, 0.f) + 1e-6f) * inv;
            float y3 = (fmaxf(x.w + bv.w, 0.f) + 1e-6f) * inv;
            float q0 = y0 * y0, q1 = y1 * y1, q2 = y2 * y2, q3 = y3 * y3;
            float s2 = q0 + q1 + q2 + q3;
            float s4 = q0 * q0 + q1 * q1 + q2 * q2 + q3 * q3;
            #pragma unroll
            for (int off = 16; off; off >>= 1) {
                s2 += __shfl_xor_sync(0xffffffffu, s2, off);
                s4 += __shfl_xor_sync(0xffffffffu, s4, off);
            }
            float rsc = sqrtf(s2) / (sqrtf(s4) + 1e-8f);
            float4 o;
            o.x = rsc * q0; o.y = rsc * q1; o.z = rsc * q2; o.w = rsc * q3;
            size_t base = (size_t)(row0 + r) * ldc + colb + lane * 4;
            if (Cf) *(float4*)(Cf + base) = o;
            if (OutH) {
                __nv_bfloat16 h0, h1, h2, h3, l0, l1, l2, l3;
                split_bf(o.x, h0, l0); split_bf(o.y, h1, l1);
                split_bf(o.z, h2, l2); split_bf(o.w, h3, l3);
                uint2 hv = { pack_bf2(h0, h1), pack_bf2(h2, h3) };
                uint2 lv = { pack_bf2(l0, l1), pack_bf2(l2, l3) };
                *(uint2*)(OutH + base) = hv;
                *(uint2*)(OutL + base) = lv;
            }
        }
    } else {
        #pragma unroll 2
        for (int it = 0; it < 16; it++) {
            int idx = it * 256 + tid;
            int r = idx >> 5, c4 = idx & 31;
            float4 v = *(float4*)&Cs[r * C_LD + c4 * 4];
            if (bias) {
                const float4 bv = *(const float4*)(bias + colb + c4 * 4);
                v.x += bv.x; v.y += bv.y; v.z += bv.z; v.w += bv.w;
            }
            size_t base = (size_t)(row0 + r) * ldc + colb + c4 * 4;
            if (Cf) *(float4*)(Cf + base) = v;
            if (OutH) {
                __nv_bfloat16 h0, h1, h2, h3, l0, l1, l2, l3;
                split_bf(v.x, h0, l0); split_bf(v.y, h1, l1);
                split_bf(v.z, h2, l2); split_bf(v.w, h3, l3);
                uint2 hv = { pack_bf2(h0, h1), pack_bf2(h2, h3) };
                uint2 lv = { pack_bf2(l0, l1), pack_bf2(l2, l3) };
                *(uint2*)(OutH + base) = hv;
                *(uint2*)(OutL + base) = lv;
            }
        }
    }
}

// ---------------- ktv via mma: C[m][d] = sum_n P[n][m] * V[n][d], per head ----------------
// P, V pre-split bf16 in global [n][h*128+col]. Trans ldmatrix for both operands.
#define T_PH 0
#define T_PL 16384
#define T_VH 32768
#define T_VL 49152
#define KTV_SMEM 65536

__global__ void __launch_bounds__(256, 2) ktv_mma() {
    extern __shared__ __align__(16) char smem[];
    const uint32_t sb = smem_u32(smem);
    const int h = blockIdx.x;
    const int chunk = blockIdx.y;
    const int tid = threadIdx.x;
    const int lane = tid & 31, warp = tid >> 5;
    const int wm = warp >> 2, wn = warp & 3;
    const int n0 = chunk * (NR / KC2);   // 512 rows per chunk

    float acc[4][4][4];
    #pragma unroll
    for (int i = 0; i < 4; i++)
        #pragma unroll
        for (int j = 0; j < 4; j++)
            #pragma unroll
            for (int e = 0; e < 4; e++) acc[i][j][e] = 0.f;
    float ks = 0.f;

    // trans-ldmatrix address components (row = k index within stage, col in elements)
    const uint32_t a_kr = (lane & 7) + ((lane >> 4) & 1) * 8;     // + kk*16
    const uint32_t a_cl = wm * 64 + ((lane >> 3) & 1) * 8;        // + mi*16
    const uint32_t b_kr = (lane & 7) + ((lane >> 3) & 1) * 8;     // + kk*16
    const uint32_t b_cl = wn * 32 + ((lane >> 4) & 1) * 8;        // + nj*16

    for (int s = 0; s < (NR / KC2) / 64; s++) {
        const int nb = n0 + s * 64;
        // stage P and V tiles [64][128] hi/lo (256B swizzled rows)
        #pragma unroll 2
        for (int it = 0; it < 4; it++) {
            int idx = it * 256 + tid;
            int r = idx >> 4, c16 = idx & 15;
            size_t gb = (size_t)(nb + r) * HD + h * DD + c16 * 8;
            uint32_t off = SWZ((uint32_t)(r * 256 + c16 * 16));
            *(uint4*)(smem + T_PH + off) = *(const uint4*)(g_Kh + gb);
            *(uint4*)(smem + T_PL + off) = *(const uint4*)(g_Kl + gb);
            *(uint4*)(smem + T_VH + off) = *(const uint4*)(g_Vh + gb);
            *(uint4*)(smem + T_VL + off) = *(const uint4*)(g_Vl + gb);
        }
        __syncthreads();

        #pragma unroll
        for (int pass = 0; pass < 3; pass++) {
            const uint32_t Ap = sb + ((pass == 2) ? T_PL : T_PH);
            const uint32_t Bp = sb + ((pass == 1) ? T_VL : T_VH);
            #pragma unroll
            for (int kk = 0; kk < 4; kk++) {
                uint32_t a[4][4];
                #pragma unroll
                for (int mi = 0; mi < 4; mi++)
                    ldsm_x4_t(a[mi][0], a[mi][1], a[mi][2], a[mi][3],
                              Ap + SWZ((kk * 16 + a_kr) * 256 + (a_cl + mi * 16) * 2));
                uint32_t b[2][4];
                #pragma unroll
                for (int nj = 0; nj < 2; nj++)
                    ldsm_x4_t(b[nj][0], b[nj][1], b[nj][2], b[nj][3],
                              Bp + SWZ((kk * 16 + b_kr) * 256 + (b_cl + nj * 16) * 2));
                #pragma unroll
                for (int mi = 0; mi < 4; mi++)
                    #pragma unroll
                    for (int nbt = 0; nbt < 4; nbt++)
                        mma_bf16(acc[mi][nbt], a[mi][0], a[mi][1], a[mi][2], a[mi][3],
                                 b[nbt >> 1][(nbt & 1) * 2], b[nbt >> 1][(nbt & 1) * 2 + 1]);
            }
        }
        // ksum: column sums of P (hi+lo) over this stage
        if (tid < 128) {
            #pragma unroll 4
            for (int r = 0; r < 64; r++) {
                uint32_t off = SWZ((uint32_t)(r * 256 + tid * 2));
                ks += __bfloat162float(*(const __nv_bfloat16*)(smem + T_PH + off))
                    + __bfloat162float(*(const __nv_bfloat16*)(smem + T_PL + off));
            }
        }
        __syncthreads();
    }

    float* out = g_ktvp + ((size_t)chunk * NH + h) * (DD * DD);
    const int rr = wm * 64 + (lane >> 2);
    const int cc = wn * 32 + 2 * (lane & 3);
    #pragma unroll
    for (int mi = 0; mi < 4; mi++)
        #pragma unroll
        for (int nbt = 0; nbt < 4; nbt++) {
            int r = rr + mi * 16;
            int c = cc + (nbt >> 1) * 16 + (nbt & 1) * 8;
            *(float2*)&out[r * DD + c]       = *(float2*)&acc[mi][nbt][0];
            *(float2*)&out[(r + 8) * DD + c] = *(float2*)&acc[mi][nbt][2];
        }
    if (tid < 128) g_ksump[(chunk * NH + h) * DD + tid] = ks;
}

// reduce partials; write ktv^T bf16-split for the numerator GEMM
__global__ void ktv_reduce_kernel() {
    int idx = blockIdx.x * blockDim.x + threadIdx.x;
    if (idx < NH * DD * DD) {
        float s = 0.f;
        #pragma unroll 8
        for (int c = 0; c < KC2; c++) s += g_ktvp[(size_t)c * NH * DD * DD + idx];
        int h = idx >> 14, m = (idx >> 7) & 127, d = idx & 127;
        __nv_bfloat16 hi, lo;
        split_bf(s, hi, lo);
        g_ktvTh[(h << 14) + (d << 7) + m] = hi;
        g_ktvTl[(h << 14) + (d << 7) + m] = lo;
    }
    if (idx < NH * DD) {
        float s = 0.f;
        #pragma unroll 8
        for (int c = 0; c < KC2; c++) s += g_ksump[c * NH * DD + idx];
        g_ksum[idx] = s;
    }
}

// ---------------- combine: one warp per row -> out[n][129] ----------------
__global__ void combine_kernel(float* __restrict__ out) {
    int n = blockIdx.x * 8 + (threadIdx.x >> 5);
    int lane = threadIdx.x & 31;
    const float* phiq = g_bufA + (size_t)n * HD;
    const float* num  = g_bufB + (size_t)n * HD;

    float dinv[NH];
    #pragma unroll
    for (int h = 0; h < NH; h++) {
        float4 q = *((const float4*)(phiq + h * DD) + lane);
        float4 s = *((const float4*)(g_ksum + h * DD) + lane);
        float d = q.x * s.x + q.y * s.y + q.z * s.z + q.w * s.w;
        #pragma unroll
        for (int off = 16; off; off >>= 1) d += __shfl_xor_sync(0xffffffffu, d, off);
        dinv[h] = 1.f / (d + 1e-6f);
    }

    float vals[4];
    float ssum = 0.f;
    #pragma unroll
    for (int c = 0; c < 4; c++) {
        int dcol = c * 32 + lane;
        float acc = 0.f;
        #pragma unroll
        for (int h = 0; h < NH; h++) acc += num[h * DD + dcol] * dinv[h];
        acc = acc * 0.125f + g_att[(size_t)n * DD + dcol];
        vals[c] = acc;
        ssum += acc * acc;
    }
    #pragma unroll
    for (int off = 16; off; off >>= 1) ssum += __shfl_xor_sync(0xffffffffu, ssum, off);
    float t = sqrtf(ssum + 1.0f);

    float* op = out + (size_t)n * 129;
    if (lane == 0) op[0] = t;
    #pragma unroll
    for (int c = 0; c < 4; c++) op[1 + c * 32 + lane] = vals[c];
}

// ---------------- launch ----------------
extern "C" void kernel_launch(void* const* d_in, const int* in_sizes, int n_in,
                              void* d_out, int out_size) {
    const float* xq   = (const float*)d_in[0];
    const float* xs   = (const float*)d_in[1];
    const float* Wq_w = (const float*)d_in[2];
    const float* Wq_b = (const float*)d_in[3];
    const float* Wk_w = (const float*)d_in[4];
    const float* Wk_b = (const float*)d_in[5];
    const float* Wv_w = (const float*)d_in[6];
    const float* Wv_b = (const float*)d_in[7];
    const float* vmw  = (const float*)d_in[8];
    const float* vmb  = (const float*)d_in[9];
    const float* nsc  = (const float*)d_in[10];
    float* out = (float*)d_out;

    float *pcfuse, *pbufA, *pbufB, *patt;
    __nv_bfloat16 *pWqh, *pWql, *pWkh, *pWkl, *pWvh, *pWvl, *pWfh, *pWfl, *pKTh, *pKTl;
    __nv_bfloat16 *pKh, *pKl, *pVh, *pVl;
    cudaGetSymbolAddress((void**)&pcfuse, g_cfuse);
    cudaGetSymbolAddress((void**)&pbufA, g_bufA);
    cudaGetSymbolAddress((void**)&pbufB, g_bufB);
    cudaGetSymbolAddress((void**)&patt, g_att);
    cudaGetSymbolAddress((void**)&pWqh, g_Wqh);
    cudaGetSymbolAddress((void**)&pWql, g_Wql);
    cudaGetSymbolAddress((void**)&pWkh, g_Wkh);
    cudaGetSymbolAddress((void**)&pWkl, g_Wkl);
    cudaGetSymbolAddress((void**)&pWvh, g_Wvh);
    cudaGetSymbolAddress((void**)&pWvl, g_Wvl);
    cudaGetSymbolAddress((void**)&pWfh, g_WfTh);
    cudaGetSymbolAddress((void**)&pWfl, g_WfTl);
    cudaGetSymbolAddress((void**)&pKTh, g_ktvTh);
    cudaGetSymbolAddress((void**)&pKTl, g_ktvTl);
    cudaGetSymbolAddress((void**)&pKh, g_Kh);
    cudaGetSymbolAddress((void**)&pKl, g_Kl);
    cudaGetSymbolAddress((void**)&pVh, g_Vh);
    cudaGetSymbolAddress((void**)&pVl, g_Vl);

    cudaFuncSetAttribute(mm_gemm, cudaFuncAttributeMaxDynamicSharedMemorySize, MM_SMEM);
    cudaFuncSetAttribute(ktv_mma, cudaFuncAttributeMaxDynamicSharedMemorySize, KTV_SMEM);

    prep_kernel<<<(3 * 131072 + DD * DD + 255) / 256, 256>>>(Wq_w, Wk_w, Wv_w);
    wfuse_kernel<<<(DD * DD + 255) / 256, 256>>>(Wv_b, vmw, vmb);

    dim3 gproj(NR / 128, NH);
    // K projection + fused phi -> bf16 split (no fp32 out)
    mm_gemm<<<gproj, 256, MM_SMEM>>>(xs, DD, 0, pWkh, pWkl, Wk_b, nullptr, HD, nsc, pKh, pKl);
    // V projection -> bf16 split
    mm_gemm<<<gproj, 256, MM_SMEM>>>(xs, DD, 0, pWvh, pWvl, Wv_b, nullptr, HD, nullptr, pVh, pVl);
    // ktv + ksum on tensor cores, deterministic two-stage
    ktv_mma<<<dim3(NH, KC2), 256, KTV_SMEM>>>();
    ktv_reduce_kernel<<<(NH * DD * DD + 255) / 256, 256>>>();
    // Q projection + fused phi -> fp32 bufA
    mm_gemm<<<gproj, 256, MM_SMEM>>>(xq, DD, 0, pWqh, pWql, Wq_b, pbufA, HD, nsc, nullptr, nullptr);
    // numerator: per-head phi_qs @ ktv[h] -> bufB
    mm_gemm<<<gproj, 256, MM_SMEM>>>(pbufA, HD, 1, pKTh, pKTl, nullptr, pbufB, HD, nullptr, nullptr, nullptr);
    // fused vss: xs @ WfuseT -> att
    mm_gemm<<<dim3(NR / 128, 1), 256, MM_SMEM>>>(xs, DD, 0, pWfh, pWfl, pcfuse, patt, DD, nullptr, nullptr, nullptr);
    // combine + time coordinate
    combine_kernel<<<NR / 8, 256>>>(out);
}

// round 5
// speedup vs baseline: 1.9559x; 1.2449x over previous
#include <cuda_runtime.h>
#include <cuda_bf16.h>
#include <cstdint>
#include <math.h>

#define NR 32768
#define NH 8
#define DD 128
#define HD 1024     // NH * DD
#define KC2 64      // split-K chunks for ktv (512 rows each)

// ---------------- scratch (static device memory; no allocations) ----------------
__device__ __nv_bfloat16 g_Wqh[DD * HD], g_Wql[DD * HD];   // [h*128+o][i] K-major
__device__ __nv_bfloat16 g_Wkh[DD * HD], g_Wkl[DD * HD];
__device__ __nv_bfloat16 g_Wvh[DD * HD], g_Wvl[DD * HD];
__device__ float g_Wvm[DD * DD];                           // mean_h Wv_w -> [d][i]
__device__ __nv_bfloat16 g_WfTh[DD * DD], g_WfTl[DD * DD]; // fused vss weight [o][i]
__device__ float g_cfuse[DD];
__device__ float g_bufA[(size_t)NR * HD];   // phi_qs (fp32, for combine denominator)
__device__ float g_bufB[(size_t)NR * HD];   // num
__device__ float g_att[(size_t)NR * DD];    // fused vss mean
__device__ __nv_bfloat16 g_Xsh[(size_t)NR * DD], g_Xsl[(size_t)NR * DD];  // xs split
__device__ __nv_bfloat16 g_Xqh[(size_t)NR * DD], g_Xql[(size_t)NR * DD];  // xq split
__device__ __nv_bfloat16 g_Kh[(size_t)NR * HD], g_Kl[(size_t)NR * HD];    // phi_ks split
__device__ __nv_bfloat16 g_Vh[(size_t)NR * HD], g_Vl[(size_t)NR * HD];    // v split
__device__ __nv_bfloat16 g_Qh[(size_t)NR * HD], g_Ql[(size_t)NR * HD];    // phi_qs split
__device__ __nv_bfloat16 g_ktvTh[NH * DD * DD], g_ktvTl[NH * DD * DD];    // [h][d][m]
__device__ float g_ksum[NH * DD];
__device__ float g_ktvp[(size_t)KC2 * NH * DD * DD];
__device__ float g_ksump[KC2 * NH * DD];

// ---------------- helpers ----------------
__device__ __forceinline__ uint32_t smem_u32(const void* p) {
    uint32_t a;
    asm("{ .reg .u64 t; cvta.to.shared.u64 t, %1; cvt.u32.u64 %0, t; }" : "=r"(a) : "l"(p));
    return a;
}
__device__ __forceinline__ uint32_t pack_bf2(__nv_bfloat16 a, __nv_bfloat16 b) {
    __nv_bfloat162 t; t.x = a; t.y = b;
    return *reinterpret_cast<uint32_t*>(&t);
}
__device__ __forceinline__ void split_bf(float x, __nv_bfloat16& h, __nv_bfloat16& l) {
    h = __float2bfloat16_rn(x);
    l = __float2bfloat16_rn(x - __bfloat162float(h));
}
#define SWZ(o)  ((o) ^ ((((o) >> 8) & 7) << 4))
#define SWZ1(o) ((o) ^ ((((o) >> 7) & 7) << 4))

__device__ __forceinline__ void ldsm_x4(uint32_t& r0, uint32_t& r1, uint32_t& r2,
                                        uint32_t& r3, uint32_t addr) {
    asm volatile("ldmatrix.sync.aligned.m8n8.x4.shared.b16 {%0,%1,%2,%3}, [%4];"
                 : "=r"(r0), "=r"(r1), "=r"(r2), "=r"(r3) : "r"(addr));
}
__device__ __forceinline__ void ldsm_x4_t(uint32_t& r0, uint32_t& r1, uint32_t& r2,
                                          uint32_t& r3, uint32_t addr) {
    asm volatile("ldmatrix.sync.aligned.m8n8.x4.trans.shared.b16 {%0,%1,%2,%3}, [%4];"
                 : "=r"(r0), "=r"(r1), "=r"(r2), "=r"(r3) : "r"(addr));
}
__device__ __forceinline__ void mma_bf16(float* c, uint32_t a0, uint32_t a1,
                                         uint32_t a2, uint32_t a3,
                                         uint32_t b0, uint32_t b1) {
    asm volatile("mma.sync.aligned.m16n8k16.row.col.f32.bf16.bf16.f32 "
                 "{%0,%1,%2,%3}, {%4,%5,%6,%7}, {%8,%9}, {%0,%1,%2,%3};"
                 : "+f"(c[0]), "+f"(c[1]), "+f"(c[2]), "+f"(c[3])
                 : "r"(a0), "r"(a1), "r"(a2), "r"(a3), "r"(b0), "r"(b1));
}

// ---------------- input split: fp32 -> bf16 hi/lo ----------------
__global__ void split_x_kernel(const float* __restrict__ xs, const float* __restrict__ xq) {
    int idx = blockIdx.x * blockDim.x + threadIdx.x;   // over NR*DD/4
    if (idx >= NR * DD / 4) return;
    float4 s = *(const float4*)(xs + (size_t)idx * 4);
    float4 q = *(const float4*)(xq + (size_t)idx * 4);
    __nv_bfloat16 h0, h1, h2, h3, l0, l1, l2, l3;
    split_bf(s.x, h0, l0); split_bf(s.y, h1, l1);
    split_bf(s.z, h2, l2); split_bf(s.w, h3, l3);
    uint2 hv = { pack_bf2(h0, h1), pack_bf2(h2, h3) };
    uint2 lv = { pack_bf2(l0, l1), pack_bf2(l2, l3) };
    *(uint2*)(g_Xsh + (size_t)idx * 4) = hv;
    *(uint2*)(g_Xsl + (size_t)idx * 4) = lv;
    split_bf(q.x, h0, l0); split_bf(q.y, h1, l1);
    split_bf(q.z, h2, l2); split_bf(q.w, h3, l3);
    hv.x = pack_bf2(h0, h1); hv.y = pack_bf2(h2, h3);
    lv.x = pack_bf2(l0, l1); lv.y = pack_bf2(l2, l3);
    *(uint2*)(g_Xqh + (size_t)idx * 4) = hv;
    *(uint2*)(g_Xql + (size_t)idx * 4) = lv;
}

// ---------------- weight prep ----------------
__global__ void prep_kernel(const float* __restrict__ Wq,
                            const float* __restrict__ Wk,
                            const float* __restrict__ Wv) {
    int idx = blockIdx.x * blockDim.x + threadIdx.x;
    if (idx < 3 * 131072) {
        int which = idx / 131072;
        int e = idx % 131072;
        const float* src = (which == 0) ? Wq : (which == 1) ? Wk : Wv;
        __nv_bfloat16 h, l;
        split_bf(src[e], h, l);
        if (which == 0)      { g_Wqh[e] = h; g_Wql[e] = l; }
        else if (which == 1) { g_Wkh[e] = h; g_Wkl[e] = l; }
        else                 { g_Wvh[e] = h; g_Wvl[e] = l; }
    } else if (idx < 3 * 131072 + DD * DD) {
        int e = idx - 3 * 131072;
        int i = e & 127, d = e >> 7;
        float s = 0.f;
        #pragma unroll
        for (int h = 0; h < NH; h++) s += Wv[((size_t)(h * DD + d)) * DD + i];
        g_Wvm[d * DD + i] = s * 0.125f;
    }
}

__global__ void wfuse_kernel(const float* __restrict__ Wv_b,
                             const float* __restrict__ vmw,
                             const float* __restrict__ vmb) {
    int idx = blockIdx.x * blockDim.x + threadIdx.x;
    if (idx >= DD * DD) return;
    int o = idx & 127, i = idx >> 7;
    float acc = 0.f;
    for (int d = 0; d < DD; d++) acc += g_Wvm[d * DD + i] * vmw[o * DD + d];
    __nv_bfloat16 h, l;
    split_bf(acc, h, l);
    g_WfTh[o * DD + i] = h;
    g_WfTl[o * DD + i] = l;
    if (idx < DD) {
        float c = 0.f;
        for (int d = 0; d < DD; d++) {
            float bm = 0.f;
            #pragma unroll
            for (int hh = 0; hh < NH; hh++) bm += Wv_b[hh * DD + d];
            c += 0.125f * bm * vmw[idx * DD + d];
        }
        g_cfuse[idx] = c + vmb[idx];
    }
}

// ---------------- mma.sync bf16-pair GEMM (pre-split A), k-chunked ----------------
#define S_AH 0
#define S_AL 16384
#define S_BH 32768
#define S_BL 49152
#define C_LD 132
#define MM_SMEM (128 * C_LD * 4)   // 67584

__global__ void __launch_bounds__(256, 2) mm_gemm(
    const __nv_bfloat16* __restrict__ Ah, const __nv_bfloat16* __restrict__ Al,
    int lda, int per_head,
    const __nv_bfloat16* __restrict__ Bh, const __nv_bfloat16* __restrict__ Bl,
    const float* __restrict__ bias, float* __restrict__ Cf, int ldc,
    const float* __restrict__ nsc,
    __nv_bfloat16* __restrict__ OutH, __nv_bfloat16* __restrict__ OutL) {
    extern __shared__ __align__(16) char smem[];
    const uint32_t sb = smem_u32(smem);
    float* Cs = (float*)smem;
    const int tid = threadIdx.x;
    const int lane = tid & 31, warp = tid >> 5;
    const int wm = warp >> 2, wn = warp & 3;
    const int row0 = blockIdx.x * 128;
    const int colb = blockIdx.y * 128;
    const int aoff = per_head ? colb : 0;
    Bh += (size_t)colb * DD;
    Bl += (size_t)colb * DD;

    float acc[4][4][4];
    #pragma unroll
    for (int i = 0; i < 4; i++)
        #pragma unroll
        for (int j = 0; j < 4; j++)
            #pragma unroll
            for (int e = 0; e < 4; e++) acc[i][j][e] = 0.f;

    const uint32_t a_row = wm * 64 + (lane & 15);
    const uint32_t a_cb  = (lane >> 4) * 16;
    const uint32_t b_row = wn * 32 + (lane & 7) + ((lane >> 4) & 1) * 8;
    const uint32_t b_cb  = ((lane >> 3) & 1) * 16;

    #pragma unroll
    for (int kc = 0; kc < 2; kc++) {
        // stage: 4 panels of 128x64 bf16 (uint4 copies, SW1 128B rows)
        #pragma unroll 2
        for (int it = 0; it < 4; it++) {
            int idx = it * 256 + tid;
            int r = idx >> 3, c8 = idx & 7;
            size_t ga = (size_t)(row0 + r) * lda + aoff + kc * 64 + c8 * 8;
            size_t gb = (size_t)r * DD + kc * 64 + c8 * 8;
            uint32_t off = SWZ1((uint32_t)(r * 128 + c8 * 16));
            *(uint4*)(smem + S_AH + off) = *(const uint4*)(Ah + ga);
            *(uint4*)(smem + S_AL + off) = *(const uint4*)(Al + ga);
            *(uint4*)(smem + S_BH + off) = *(const uint4*)(Bh + gb);
            *(uint4*)(smem + S_BL + off) = *(const uint4*)(Bl + gb);
        }
        __syncthreads();

        #pragma unroll
        for (int k = 0; k < 4; k++) {
            const uint32_t kb = k * 32;
            uint32_t ah[4][4], al[4][4], b[2][4];
            #pragma unroll
            for (int mi = 0; mi < 4; mi++) {
                uint32_t ra = SWZ1((a_row + mi * 16) * 128 + kb + a_cb);
                ldsm_x4(ah[mi][0], ah[mi][1], ah[mi][2], ah[mi][3], sb + S_AH + ra);
                ldsm_x4(al[mi][0], al[mi][1], al[mi][2], al[mi][3], sb + S_AL + ra);
            }
            // Bh: AhBh + AlBh
            #pragma unroll
            for (int nj = 0; nj < 2; nj++)
                ldsm_x4(b[nj][0], b[nj][1], b[nj][2], b[nj][3],
                        sb + S_BH + SWZ1((b_row + nj * 16) * 128 + kb + b_cb));
            #pragma unroll
            for (int mi = 0; mi < 4; mi++)
                #pragma unroll
                for (int nb = 0; nb < 4; nb++) {
                    mma_bf16(acc[mi][nb], ah[mi][0], ah[mi][1], ah[mi][2], ah[mi][3],
                             b[nb >> 1][(nb & 1) * 2], b[nb >> 1][(nb & 1) * 2 + 1]);
                    mma_bf16(acc[mi][nb], al[mi][0], al[mi][1], al[mi][2], al[mi][3],
                             b[nb >> 1][(nb & 1) * 2], b[nb >> 1][(nb & 1) * 2 + 1]);
                }
            // Bl: AhBl
            #pragma unroll
            for (int nj = 0; nj < 2; nj++)
                ldsm_x4(b[nj][0], b[nj][1], b[nj][2], b[nj][3],
                        sb + S_BL + SWZ1((b_row + nj * 16) * 128 + kb + b_cb));
            #pragma unroll
            for (int mi = 0; mi < 4; mi++)
                #pragma unroll
                for (int nb = 0; nb < 4; nb++)
                    mma_bf16(acc[mi][nb], ah[mi][0], ah[mi][1], ah[mi][2], ah[mi][3],
                             b[nb >> 1][(nb & 1) * 2], b[nb >> 1][(nb & 1) * 2 + 1]);
        }
        __syncthreads();
    }

    if (nsc) {
        // ---- phi epilogue: needs full-row norm; stage C in smem ----
        {
            const int rr = wm * 64 + (lane >> 2);
            const int cc = wn * 32 + 2 * (lane & 3);
            #pragma unroll
            for (int mi = 0; mi < 4; mi++)
                #pragma unroll
                for (int nb = 0; nb < 4; nb++) {
                    int r = rr + mi * 16;
                    int c = cc + (nb >> 1) * 16 + (nb & 1) * 8;
                    *(float2*)&Cs[r * C_LD + c]       = *(float2*)&acc[mi][nb][0];
                    *(float2*)&Cs[(r + 8) * C_LD + c] = *(float2*)&acc[mi][nb][2];
                }
        }
        __syncthreads();
        float inv = 1.f / (fabsf(*nsc) + 1e-6f);
        const float4 bv = *(const float4*)(bias + colb + lane * 4);
        #pragma unroll 2
        for (int i = 0; i < 16; i++) {
            int r = warp * 16 + i;
            float4 x = *(float4*)&Cs[r * C_LD + lane * 4];
            float y0 = (fmaxf(x.x + bv.x, 0.f) + 1e-6f) * inv;
            float y1 = (fmaxf(x.y + bv.y, 0.f) + 1e-6f) * inv;
            float y2 = (fmaxf(x.z + bv.z, 0.f) + 1e-6f) * inv;
            float y3 = (fmaxf(x.w + bv.w, 0.f) + 1e-6f) * inv;
            float q0 = y0 * y0, q1 = y1 * y1, q2 = y2 * y2, q3 = y3 * y3;
            float s2 = q0 + q1 + q2 + q3;
            float s4 = q0 * q0 + q1 * q1 + q2 * q2 + q3 * q3;
            #pragma unroll
            for (int off = 16; off; off >>= 1) {
                s2 += __shfl_xor_sync(0xffffffffu, s2, off);
                s4 += __shfl_xor_sync(0xffffffffu, s4, off);
            }
            float rsc = sqrtf(s2) / (sqrtf(s4) + 1e-8f);
            float4 o;
            o.x = rsc * q0; o.y = rsc * q1; o.z = rsc * q2; o.w = rsc * q3;
            size_t base = (size_t)(row0 + r) * ldc + colb + lane * 4;
            if (Cf) *(float4*)(Cf + base) = o;
            if (OutH) {
                __nv_bfloat16 h0, h1, h2, h3, l0, l1, l2, l3;
                split_bf(o.x, h0, l0); split_bf(o.y, h1, l1);
                split_bf(o.z, h2, l2); split_bf(o.w, h3, l3);
                uint2 hv = { pack_bf2(h0, h1), pack_bf2(h2, h3) };
                uint2 lv = { pack_bf2(l0, l1), pack_bf2(l2, l3) };
                *(uint2*)(OutH + base) = hv;
                *(uint2*)(OutL + base) = lv;
            }
        }
    } else {
        // ---- direct register epilogue ----
        const int rr = wm * 64 + (lane >> 2);
        const int cc = wn * 32 + 2 * (lane & 3);
        #pragma unroll
        for (int mi = 0; mi < 4; mi++)
            #pragma unroll
            for (int nb = 0; nb < 4; nb++) {
                int r = rr + mi * 16;
                int c = cc + (nb >> 1) * 16 + (nb & 1) * 8;
                float b0 = bias ? bias[colb + c] : 0.f;
                float b1 = bias ? bias[colb + c + 1] : 0.f;
                float2 v0 = { acc[mi][nb][0] + b0, acc[mi][nb][1] + b1 };
                float2 v1 = { acc[mi][nb][2] + b0, acc[mi][nb][3] + b1 };
                size_t base0 = (size_t)(row0 + r) * ldc + colb + c;
                size_t base1 = (size_t)(row0 + r + 8) * ldc + colb + c;
                if (Cf) {
                    *(float2*)(Cf + base0) = v0;
                    *(float2*)(Cf + base1) = v1;
                }
                if (OutH) {
                    __nv_bfloat16 h0, h1, l0, l1;
                    split_bf(v0.x, h0, l0); split_bf(v0.y, h1, l1);
                    *(uint32_t*)(OutH + base0) = pack_bf2(h0, h1);
                    *(uint32_t*)(OutL + base0) = pack_bf2(l0, l1);
                    split_bf(v1.x, h0, l0); split_bf(v1.y, h1, l1);
                    *(uint32_t*)(OutH + base1) = pack_bf2(h0, h1);
                    *(uint32_t*)(OutL + base1) = pack_bf2(l0, l1);
                }
            }
    }
}

// ---------------- ktv via mma: C[m][d] = sum_n P[n][m] * V[n][d], per head ----------------
#define T_PH 0
#define T_PL 16384
#define T_VH 32768
#define T_VL 49152
#define KTV_SMEM 65536

__global__ void __launch_bounds__(256, 2) ktv_mma() {
    extern __shared__ __align__(16) char smem[];
    const uint32_t sb = smem_u32(smem);
    const int h = blockIdx.x;
    const int chunk = blockIdx.y;
    const int tid = threadIdx.x;
    const int lane = tid & 31, warp = tid >> 5;
    const int wm = warp >> 2, wn = warp & 3;
    const int n0 = chunk * (NR / KC2);

    float acc[4][4][4];
    #pragma unroll
    for (int i = 0; i < 4; i++)
        #pragma unroll
        for (int j = 0; j < 4; j++)
            #pragma unroll
            for (int e = 0; e < 4; e++) acc[i][j][e] = 0.f;
    float ks = 0.f;

    const uint32_t a_kr = (lane & 7) + ((lane >> 4) & 1) * 8;
    const uint32_t a_cl = wm * 64 + ((lane >> 3) & 1) * 8;
    const uint32_t b_kr = (lane & 7) + ((lane >> 3) & 1) * 8;
    const uint32_t b_cl = wn * 32 + ((lane >> 4) & 1) * 8;

    for (int s = 0; s < (NR / KC2) / 64; s++) {
        const int nb = n0 + s * 64;
        #pragma unroll 2
        for (int it = 0; it < 4; it++) {
            int idx = it * 256 + tid;
            int r = idx >> 4, c16 = idx & 15;
            size_t gb = (size_t)(nb + r) * HD + h * DD + c16 * 8;
            uint32_t off = SWZ((uint32_t)(r * 256 + c16 * 16));
            *(uint4*)(smem + T_PH + off) = *(const uint4*)(g_Kh + gb);
            *(uint4*)(smem + T_PL + off) = *(const uint4*)(g_Kl + gb);
            *(uint4*)(smem + T_VH + off) = *(const uint4*)(g_Vh + gb);
            *(uint4*)(smem + T_VL + off) = *(const uint4*)(g_Vl + gb);
        }
        __syncthreads();

        #pragma unroll
        for (int pass = 0; pass < 3; pass++) {
            const uint32_t Ap = sb + ((pass == 2) ? T_PL : T_PH);
            const uint32_t Bp = sb + ((pass == 1) ? T_VL : T_VH);
            #pragma unroll
            for (int kk = 0; kk < 4; kk++) {
                uint32_t a[4][4];
                #pragma unroll
                for (int mi = 0; mi < 4; mi++)
                    ldsm_x4_t(a[mi][0], a[mi][1], a[mi][2], a[mi][3],
                              Ap + SWZ((kk * 16 + a_kr) * 256 + (a_cl + mi * 16) * 2));
                uint32_t b[2][4];
                #pragma unroll
                for (int nj = 0; nj < 2; nj++)
                    ldsm_x4_t(b[nj][0], b[nj][1], b[nj][2], b[nj][3],
                              Bp + SWZ((kk * 16 + b_kr) * 256 + (b_cl + nj * 16) * 2));
                #pragma unroll
                for (int mi = 0; mi < 4; mi++)
                    #pragma unroll
                    for (int nbt = 0; nbt < 4; nbt++)
                        mma_bf16(acc[mi][nbt], a[mi][0], a[mi][1], a[mi][2], a[mi][3],
                                 b[nbt >> 1][(nbt & 1) * 2], b[nbt >> 1][(nbt & 1) * 2 + 1]);
            }
        }
        if (tid < 128) {
            #pragma unroll 4
            for (int r = 0; r < 64; r++) {
                uint32_t off = SWZ((uint32_t)(r * 256 + tid * 2));
                ks += __bfloat162float(*(const __nv_bfloat16*)(smem + T_PH + off))
                    + __bfloat162float(*(const __nv_bfloat16*)(smem + T_PL + off));
            }
        }
        __syncthreads();
    }

    float* out = g_ktvp + ((size_t)chunk * NH + h) * (DD * DD);
    const int rr = wm * 64 + (lane >> 2);
    const int cc = wn * 32 + 2 * (lane & 3);
    #pragma unroll
    for (int mi = 0; mi < 4; mi++)
        #pragma unroll
        for (int nbt = 0; nbt < 4; nbt++) {
            int r = rr + mi * 16;
            int c = cc + (nbt >> 1) * 16 + (nbt & 1) * 8;
            *(float2*)&out[r * DD + c]       = *(float2*)&acc[mi][nbt][0];
            *(float2*)&out[(r + 8) * DD + c] = *(float2*)&acc[mi][nbt][2];
        }
    if (tid < 128) g_ksump[(chunk * NH + h) * DD + tid] = ks;
}

// reduce partials; write ktv^T bf16-split for the numerator GEMM
__global__ void ktv_reduce_kernel() {
    int idx = blockIdx.x * blockDim.x + threadIdx.x;
    if (idx < NH * DD * DD) {
        float s = 0.f;
        #pragma unroll 8
        for (int c = 0; c < KC2; c++) s += g_ktvp[(size_t)c * NH * DD * DD + idx];
        int h = idx >> 14, m = (idx >> 7) & 127, d = idx & 127;
        __nv_bfloat16 hi, lo;
        split_bf(s, hi, lo);
        g_ktvTh[(h << 14) + (d << 7) + m] = hi;
        g_ktvTl[(h << 14) + (d << 7) + m] = lo;
    }
    if (idx < NH * DD) {
        float s = 0.f;
        #pragma unroll 8
        for (int c = 0; c < KC2; c++) s += g_ksump[c * NH * DD + idx];
        g_ksum[idx] = s;
    }
}

// ---------------- combine: one warp per row -> out[n][129] ----------------
__global__ void combine_kernel(float* __restrict__ out) {
    int n = blockIdx.x * 8 + (threadIdx.x >> 5);
    int lane = threadIdx.x & 31;
    const float* phiq = g_bufA + (size_t)n * HD;
    const float* num  = g_bufB + (size_t)n * HD;

    float dinv[NH];
    #pragma unroll
    for (int h = 0; h < NH; h++) {
        float4 q = *((const float4*)(phiq + h * DD) + lane);
        float4 s = *((const float4*)(g_ksum + h * DD) + lane);
        float d = q.x * s.x + q.y * s.y + q.z * s.z + q.w * s.w;
        #pragma unroll
        for (int off = 16; off; off >>= 1) d += __shfl_xor_sync(0xffffffffu, d, off);
        dinv[h] = 1.f / (d + 1e-6f);
    }

    float vals[4];
    float ssum = 0.f;
    #pragma unroll
    for (int c = 0; c < 4; c++) {
        int dcol = c * 32 + lane;
        float acc = 0.f;
        #pragma unroll
        for (int h = 0; h < NH; h++) acc += num[h * DD + dcol] * dinv[h];
        acc = acc * 0.125f + g_att[(size_t)n * DD + dcol];
        vals[c] = acc;
        ssum += acc * acc;
    }
    #pragma unroll
    for (int off = 16; off; off >>= 1) ssum += __shfl_xor_sync(0xffffffffu, ssum, off);
    float t = sqrtf(ssum + 1.0f);

    float* op = out + (size_t)n * 129;
    if (lane == 0) op[0] = t;
    #pragma unroll
    for (int c = 0; c < 4; c++) op[1 + c * 32 + lane] = vals[c];
}

// ---------------- launch ----------------
extern "C" void kernel_launch(void* const* d_in, const int* in_sizes, int n_in,
                              void* d_out, int out_size) {
    const float* xq   = (const float*)d_in[0];
    const float* xs   = (const float*)d_in[1];
    const float* Wq_w = (const float*)d_in[2];
    const float* Wq_b = (const float*)d_in[3];
    const float* Wk_w = (const float*)d_in[4];
    const float* Wk_b = (const float*)d_in[5];
    const float* Wv_w = (const float*)d_in[6];
    const float* Wv_b = (const float*)d_in[7];
    const float* vmw  = (const float*)d_in[8];
    const float* vmb  = (const float*)d_in[9];
    const float* nsc  = (const float*)d_in[10];
    float* out = (float*)d_out;

    float *pcfuse, *pbufA, *pbufB, *patt;
    __nv_bfloat16 *pWqh, *pWql, *pWkh, *pWkl, *pWvh, *pWvl, *pWfh, *pWfl, *pKTh, *pKTl;
    __nv_bfloat16 *pKh, *pKl, *pVh, *pVl, *pQh, *pQl, *pXsh, *pXsl, *pXqh, *pXql;
    cudaGetSymbolAddress((void**)&pcfuse, g_cfuse);
    cudaGetSymbolAddress((void**)&pbufA, g_bufA);
    cudaGetSymbolAddress((void**)&pbufB, g_bufB);
    cudaGetSymbolAddress((void**)&patt, g_att);
    cudaGetSymbolAddress((void**)&pWqh, g_Wqh);
    cudaGetSymbolAddress((void**)&pWql, g_Wql);
    cudaGetSymbolAddress((void**)&pWkh, g_Wkh);
    cudaGetSymbolAddress((void**)&pWkl, g_Wkl);
    cudaGetSymbolAddress((void**)&pWvh, g_Wvh);
    cudaGetSymbolAddress((void**)&pWvl, g_Wvl);
    cudaGetSymbolAddress((void**)&pWfh, g_WfTh);
    cudaGetSymbolAddress((void**)&pWfl, g_WfTl);
    cudaGetSymbolAddress((void**)&pKTh, g_ktvTh);
    cudaGetSymbolAddress((void**)&pKTl, g_ktvTl);
    cudaGetSymbolAddress((void**)&pKh, g_Kh);
    cudaGetSymbolAddress((void**)&pKl, g_Kl);
    cudaGetSymbolAddress((void**)&pVh, g_Vh);
    cudaGetSymbolAddress((void**)&pVl, g_Vl);
    cudaGetSymbolAddress((void**)&pQh, g_Qh);
    cudaGetSymbolAddress((void**)&pQl, g_Ql);
    cudaGetSymbolAddress((void**)&pXsh, g_Xsh);
    cudaGetSymbolAddress((void**)&pXsl, g_Xsl);
    cudaGetSymbolAddress((void**)&pXqh, g_Xqh);
    cudaGetSymbolAddress((void**)&pXql, g_Xql);

    cudaFuncSetAttribute(mm_gemm, cudaFuncAttributeMaxDynamicSharedMemorySize, MM_SMEM);
    cudaFuncSetAttribute(ktv_mma, cudaFuncAttributeMaxDynamicSharedMemorySize, KTV_SMEM);

    split_x_kernel<<<(NR * DD / 4 + 255) / 256, 256>>>(xs, xq);
    prep_kernel<<<(3 * 131072 + DD * DD + 255) / 256, 256>>>(Wq_w, Wk_w, Wv_w);
    wfuse_kernel<<<(DD * DD + 255) / 256, 256>>>(Wv_b, vmw, vmb);

    dim3 gproj(NR / 128, NH);
    // K projection + fused phi -> bf16 split
    mm_gemm<<<gproj, 256, MM_SMEM>>>(pXsh, pXsl, DD, 0, pWkh, pWkl, Wk_b,
                                     nullptr, HD, nsc, pKh, pKl);
    // V projection -> bf16 split (direct epilogue)
    mm_gemm<<<gproj, 256, MM_SMEM>>>(pXsh, pXsl, DD, 0, pWvh, pWvl, Wv_b,
                                     nullptr, HD, nullptr, pVh, pVl);
    // ktv + ksum on tensor cores
    ktv_mma<<<dim3(NH, KC2), 256, KTV_SMEM>>>();
    ktv_reduce_kernel<<<(NH * DD * DD + 255) / 256, 256>>>();
    // Q projection + fused phi -> fp32 bufA AND bf16 split
    mm_gemm<<<gproj, 256, MM_SMEM>>>(pXqh, pXql, DD, 0, pWqh, pWql, Wq_b,
                                     pbufA, HD, nsc, pQh, pQl);
    // numerator: per-head phi_qs @ ktv[h] -> bufB (direct epilogue)
    mm_gemm<<<gproj, 256, MM_SMEM>>>(pQh, pQl, HD, 1, pKTh, pKTl, nullptr,
                                     pbufB, HD, nullptr, nullptr, nullptr);
    // fused vss: xs @ WfuseT -> att (direct epilogue)
    mm_gemm<<<dim3(NR / 128, 1), 256, MM_SMEM>>>(pXsh, pXsl, DD, 0, pWfh, pWfl, pcfuse,
                                                 patt, DD, nullptr, nullptr, nullptr);
    // combine + time coordinate
    combine_kernel<<<NR / 8, 256>>>(out);
}